// round 1
// baseline (speedup 1.0000x reference)
#include <cuda_runtime.h>
#include <cstdint>

#define B_   8
#define K_   19
#define C_   512
#define HW_  16384
#define SCH  2048        // s-chunk staged in smem
#define CC   4           // c rows per warp (register blocking)
#define NWARP 8
#define CT   (CC * NWARP)   // 32 c rows per block

// scratch: softmax numerators + reciprocal sums (allocation-free rule -> device globals)
__device__ __align__(16) float g_e[B_ * K_ * HW_];
__device__ float g_inv[B_ * K_];

// ---------------------------------------------------------------------------
// Kernel 1: per-row softmax prep. e = exp(p - rowmax), inv = 1/sum(e).
// One block per (b,k) row of 16384. Row kept in registers across passes.
// ---------------------------------------------------------------------------
__global__ __launch_bounds__(256) void softmax_k(const float* __restrict__ probs) {
    const int row = blockIdx.x;                       // b*K_ + k
    const float4* p4 = (const float4*)(probs + (size_t)row * HW_);
    float4* e4 = (float4*)(g_e + (size_t)row * HW_);
    const int tid = threadIdx.x;

    float4 v[16];
    float m = -1e30f;
#pragma unroll
    for (int i = 0; i < 16; i++) {
        v[i] = p4[tid + 256 * i];
        m = fmaxf(m, fmaxf(fmaxf(v[i].x, v[i].y), fmaxf(v[i].z, v[i].w)));
    }

    __shared__ float red[32];
#pragma unroll
    for (int off = 16; off; off >>= 1) m = fmaxf(m, __shfl_xor_sync(0xffffffffu, m, off));
    if ((tid & 31) == 0) red[tid >> 5] = m;
    __syncthreads();
    if (tid < 32) {
        float t = (tid < NWARP) ? red[tid] : -1e30f;
#pragma unroll
        for (int off = 4; off; off >>= 1) t = fmaxf(t, __shfl_xor_sync(0xffffffffu, t, off));
        if (tid == 0) red[0] = t;
    }
    __syncthreads();
    m = red[0];

    float s = 0.f;
#pragma unroll
    for (int i = 0; i < 16; i++) {
        float4 e;
        e.x = __expf(v[i].x - m);
        e.y = __expf(v[i].y - m);
        e.z = __expf(v[i].z - m);
        e.w = __expf(v[i].w - m);
        s += (e.x + e.y) + (e.z + e.w);
        e4[tid + 256 * i] = e;
    }

    __syncthreads();   // protect red[] reuse
#pragma unroll
    for (int off = 16; off; off >>= 1) s += __shfl_xor_sync(0xffffffffu, s, off);
    if ((tid & 31) == 0) red[tid >> 5] = s;
    __syncthreads();
    if (tid == 0) {
        float t = 0.f;
#pragma unroll
        for (int i = 0; i < NWARP; i++) t += red[i];
        g_inv[row] = 1.0f / t;
    }
}

// ---------------------------------------------------------------------------
// Kernel 2: out[b,c,k] = inv[b,k] * sum_s e[b,k,s] * f[b,c,s]
// Block = (c_tile of 32, b). Warp owns CC=4 c rows; lanes stride s as float2.
// e chunk (19 x 2048 fp32 = 152KB) staged in smem; f streamed from DRAM with
// distance-2 prefetch; packed fma.rn.f32x2 accumulators (2 s-lanes per reg pair).
// ---------------------------------------------------------------------------
__global__ __launch_bounds__(256, 1) void ctx_k(const float* __restrict__ feats,
                                                float* __restrict__ out) {
    extern __shared__ float es[];                     // [K_][SCH]
    const int b    = blockIdx.y;
    const int tid  = threadIdx.x;
    const int lane = tid & 31;
    const int c0   = blockIdx.x * CT + (tid >> 5) * CC;

    const float* erow = g_e + (size_t)b * K_ * HW_;
    const unsigned long long* fp[CC];
#pragma unroll
    for (int cc = 0; cc < CC; cc++)
        fp[cc] = (const unsigned long long*)(feats + ((size_t)b * C_ + c0 + cc) * HW_);

    unsigned long long acc[K_][CC];
#pragma unroll
    for (int k = 0; k < K_; k++)
#pragma unroll
        for (int cc = 0; cc < CC; cc++) acc[k][cc] = 0ULL;

    for (int s0 = 0; s0 < HW_; s0 += SCH) {
        // --- stage e chunk: 19*512 float4 loads, 38 iters of 256 threads ---
        const float4* src = (const float4*)(erow + s0);
#pragma unroll 1
        for (int idx = tid; idx < K_ * (SCH / 4); idx += 256) {
            int k = idx >> 9;           // / (SCH/4) = /512
            int j = idx & (SCH / 4 - 1);
            ((float4*)es)[idx] = src[k * (HW_ / 4) + j];
        }
        __syncthreads();

        const int base = (s0 >> 1) + lane;   // u64-element index of f[., s0 + 2*lane]

        unsigned long long fA[CC], fB[CC];
#pragma unroll
        for (int cc = 0; cc < CC; cc++) fA[cc] = fp[cc][base];
#pragma unroll
        for (int cc = 0; cc < CC; cc++) fB[cc] = fp[cc][base + 32];

#pragma unroll 1
        for (int i = 0; i < SCH / 64; i++) {
            unsigned long long fC[CC];
            const int ip = (i + 2 < SCH / 64) ? (i + 2) : i;   // harmless re-load at tail
#pragma unroll
            for (int cc = 0; cc < CC; cc++) fC[cc] = fp[cc][base + ip * 32];

            const float* ep = es + i * 64 + lane * 2;
#pragma unroll
            for (int k = 0; k < K_; k++) {
                unsigned long long e2 = *(const unsigned long long*)(ep + k * SCH);
#pragma unroll
                for (int cc = 0; cc < CC; cc++)
                    asm("fma.rn.f32x2 %0, %1, %2, %0;"
                        : "+l"(acc[k][cc]) : "l"(e2), "l"(fA[cc]));
            }
#pragma unroll
            for (int cc = 0; cc < CC; cc++) { fA[cc] = fB[cc]; fB[cc] = fC[cc]; }
        }
        __syncthreads();
    }

    // --- epilogue: fold packed halves, warp-reduce over lanes (s), scale, store ---
    const float* invp = g_inv + b * K_;
    float* orow = out + ((size_t)b * C_ + c0) * K_;
#pragma unroll
    for (int k = 0; k < K_; k++) {
#pragma unroll
        for (int cc = 0; cc < CC; cc++) {
            unsigned int lo = (unsigned int)(acc[k][cc] & 0xffffffffULL);
            unsigned int hi = (unsigned int)(acc[k][cc] >> 32);
            float v = __uint_as_float(lo) + __uint_as_float(hi);
#pragma unroll
            for (int off = 16; off; off >>= 1)
                v += __shfl_xor_sync(0xffffffffu, v, off);
            if (lane == 0)
                orow[cc * K_ + k] = v * invp[k];
        }
    }
}

// ---------------------------------------------------------------------------
extern "C" void kernel_launch(void* const* d_in, const int* in_sizes, int n_in,
                              void* d_out, int out_size) {
    const float* feats = (const float*)d_in[0];   // (8, 512, 128, 128) fp32
    const float* probs = (const float*)d_in[1];   // (8, 19, 128, 128) fp32
    float* out = (float*)d_out;                   // (8, 512, 19, 1) fp32

    // 152 KB dynamic smem for the e chunk (idempotent attribute set).
    cudaFuncSetAttribute(ctx_k, cudaFuncAttributeMaxDynamicSharedMemorySize,
                         K_ * SCH * (int)sizeof(float));

    softmax_k<<<B_ * K_, 256>>>(probs);
    ctx_k<<<dim3(C_ / CT, B_), 256, K_ * SCH * sizeof(float)>>>(feats, out);
}

// round 2
// speedup vs baseline: 1.5823x; 1.5823x over previous
#include <cuda_runtime.h>
#include <cstdint>

#define B_   8
#define K_   19
#define C_   512
#define HW_  16384
#define SCH  1024                 // s-chunk staged in smem (per buffer)
#define NCHUNK (HW_ / SCH)        // 16
#define IPC  (SCH / 64)           // 16 inner iters per chunk
#define CC   4                    // c rows per warp
#define NWARP 8
#define CT   (CC * NWARP)         // 32 c rows per block
#define SMEM_FLOATS (2 * K_ * SCH)

typedef unsigned long long u64;

// scratch (allocation-free rule -> device globals)
__device__ __align__(16) float g_e[B_ * K_ * HW_];
__device__ float g_inv[B_ * K_];

// ---------------------------------------------------------------------------
// Kernel 1: e = exp(p - rowmax), inv = 1/sum(e). One block per (b,k) row.
// ---------------------------------------------------------------------------
__global__ __launch_bounds__(256) void softmax_k(const float* __restrict__ probs) {
    const int row = blockIdx.x;
    const float4* p4 = (const float4*)(probs + (size_t)row * HW_);
    float4* e4 = (float4*)(g_e + (size_t)row * HW_);
    const int tid = threadIdx.x;

    float4 v[16];
    float m = -1e30f;
#pragma unroll
    for (int i = 0; i < 16; i++) {
        v[i] = p4[tid + 256 * i];
        m = fmaxf(m, fmaxf(fmaxf(v[i].x, v[i].y), fmaxf(v[i].z, v[i].w)));
    }

    __shared__ float red[32];
#pragma unroll
    for (int off = 16; off; off >>= 1) m = fmaxf(m, __shfl_xor_sync(0xffffffffu, m, off));
    if ((tid & 31) == 0) red[tid >> 5] = m;
    __syncthreads();
    if (tid < 32) {
        float t = (tid < NWARP) ? red[tid] : -1e30f;
#pragma unroll
        for (int off = 4; off; off >>= 1) t = fmaxf(t, __shfl_xor_sync(0xffffffffu, t, off));
        if (tid == 0) red[0] = t;
    }
    __syncthreads();
    m = red[0];

    float s = 0.f;
#pragma unroll
    for (int i = 0; i < 16; i++) {
        float4 e;
        e.x = __expf(v[i].x - m);
        e.y = __expf(v[i].y - m);
        e.z = __expf(v[i].z - m);
        e.w = __expf(v[i].w - m);
        s += (e.x + e.y) + (e.z + e.w);
        e4[tid + 256 * i] = e;
    }

    __syncthreads();
#pragma unroll
    for (int off = 16; off; off >>= 1) s += __shfl_xor_sync(0xffffffffu, s, off);
    if ((tid & 31) == 0) red[tid >> 5] = s;
    __syncthreads();
    if (tid == 0) {
        float t = 0.f;
#pragma unroll
        for (int i = 0; i < NWARP; i++) t += red[i];
        g_inv[row] = 1.0f / t;
    }
}

// ---------------------------------------------------------------------------
// helpers
// ---------------------------------------------------------------------------
__device__ __forceinline__ void cp16(uint32_t saddr, const void* gaddr) {
    asm volatile("cp.async.cg.shared.global [%0], [%1], 16;" :: "r"(saddr), "l"(gaddr));
}
__device__ __forceinline__ void cp_commit() {
    asm volatile("cp.async.commit_group;");
}
template <int N>
__device__ __forceinline__ void cp_wait() {
    asm volatile("cp.async.wait_group %0;" :: "n"(N));
}

// ---------------------------------------------------------------------------
// Kernel 2: out[b,c,k] = inv[b,k] * sum_s e[b,k,s] * f[b,c,s]
//   - e chunks double-buffered in smem via cp.async (overlapped staging)
//   - per-iteration e loads in pipelined k-groups of 5 (LDS latency hidden)
//   - f streamed with continuous distance-2 prefetch across chunk boundaries
//   - packed fma.rn.f32x2 accumulators (2 s-lanes per 64-bit reg pair)
// ---------------------------------------------------------------------------
__global__ __launch_bounds__(256, 1) void ctx_k(const float* __restrict__ feats,
                                                float* __restrict__ out) {
    extern __shared__ float es[];                     // [2][K_][SCH]
    const int b    = blockIdx.y;
    const int tid  = threadIdx.x;
    const int lane = tid & 31;
    const int c0   = blockIdx.x * CT + (tid >> 5) * CC;

    const float* erow = g_e + (size_t)b * K_ * HW_;
    const uint32_t smem_base = (uint32_t)__cvta_generic_to_shared(es);

    // f base: lane holds a float2 column; row cc at immediate offset cc*HW_/2 u64
    const u64* fbase = (const u64*)(feats + ((size_t)b * C_ + c0) * HW_) + lane;

    u64 acc[K_][CC];
#pragma unroll
    for (int k = 0; k < K_; k++)
#pragma unroll
        for (int cc = 0; cc < CC; cc++) acc[k][cc] = 0ULL;

    // ---- stage chunk 0 into buffer 0 ----
    {
        const float4* src = (const float4*)erow;      // s0 = 0
#pragma unroll 1
        for (int idx = tid; idx < K_ * (SCH / 4); idx += 256) {
            int k = idx >> 8;                         // / (SCH/4) = /256
            int j = idx & (SCH / 4 - 1);
            cp16(smem_base + (uint32_t)(idx << 4),
                 src + k * (HW_ / 4) + j);
        }
        cp_commit();
    }

    // ---- f prefetch (distance 2, continuous over the whole s range) ----
    u64 fA[CC], fB[CC];
#pragma unroll
    for (int cc = 0; cc < CC; cc++) fA[cc] = fbase[cc * (HW_ / 2)];
#pragma unroll
    for (int cc = 0; cc < CC; cc++) fB[cc] = fbase[cc * (HW_ / 2) + 32];

#pragma unroll 1
    for (int c = 0; c < NCHUNK; c++) {
        __syncthreads();                              // buffer (c+1)&1 free to refill
        if (c + 1 < NCHUNK) {
            const float4* src = (const float4*)(erow + (c + 1) * SCH);
            const uint32_t boff = ((c + 1) & 1) * (K_ * SCH * 4);
#pragma unroll 1
            for (int idx = tid; idx < K_ * (SCH / 4); idx += 256) {
                int k = idx >> 8;
                int j = idx & (SCH / 4 - 1);
                cp16(smem_base + boff + (uint32_t)(idx << 4),
                     src + k * (HW_ / 4) + j);
            }
            cp_commit();
            cp_wait<1>();                             // chunk c staged
        } else {
            cp_wait<0>();
        }
        __syncthreads();

        const float* esc = es + (c & 1) * (K_ * SCH);

#pragma unroll 1
        for (int ii = 0; ii < IPC; ii++) {
            const int i = c * IPC + ii;

            // f prefetch for i+2 (clamped harmlessly at the tail)
            const int ip = (i + 2 < NCHUNK * IPC) ? (i + 2) : i;
            u64 fC[CC];
#pragma unroll
            for (int cc = 0; cc < CC; cc++)
                fC[cc] = fbase[cc * (HW_ / 2) + ip * 32];

            const float* ep = esc + ii * 64 + lane * 2;

            // pipelined k-groups of 5/5/5/4 (double-buffered e registers)
            u64 e0[5], e1[5];
#pragma unroll
            for (int j = 0; j < 5; j++) e0[j] = *(const u64*)(ep + j * SCH);
#pragma unroll
            for (int j = 0; j < 5; j++) e1[j] = *(const u64*)(ep + (5 + j) * SCH);

#pragma unroll
            for (int j = 0; j < 5; j++)
#pragma unroll
                for (int cc = 0; cc < CC; cc++)
                    asm("fma.rn.f32x2 %0, %1, %2, %0;"
                        : "+l"(acc[j][cc]) : "l"(e0[j]), "l"(fA[cc]));

#pragma unroll
            for (int j = 0; j < 5; j++) e0[j] = *(const u64*)(ep + (10 + j) * SCH);

#pragma unroll
            for (int j = 0; j < 5; j++)
#pragma unroll
                for (int cc = 0; cc < CC; cc++)
                    asm("fma.rn.f32x2 %0, %1, %2, %0;"
                        : "+l"(acc[5 + j][cc]) : "l"(e1[j]), "l"(fA[cc]));

#pragma unroll
            for (int j = 0; j < 4; j++) e1[j] = *(const u64*)(ep + (15 + j) * SCH);

#pragma unroll
            for (int j = 0; j < 5; j++)
#pragma unroll
                for (int cc = 0; cc < CC; cc++)
                    asm("fma.rn.f32x2 %0, %1, %2, %0;"
                        : "+l"(acc[10 + j][cc]) : "l"(e0[j]), "l"(fA[cc]));

#pragma unroll
            for (int j = 0; j < 4; j++)
#pragma unroll
                for (int cc = 0; cc < CC; cc++)
                    asm("fma.rn.f32x2 %0, %1, %2, %0;"
                        : "+l"(acc[15 + j][cc]) : "l"(e1[j]), "l"(fA[cc]));

#pragma unroll
            for (int cc = 0; cc < CC; cc++) { fA[cc] = fB[cc]; fB[cc] = fC[cc]; }
        }
    }

    // ---- epilogue: fold packed halves, warp-reduce over s-lanes, scale, store ----
    const float* invp = g_inv + b * K_;
    float* orow = out + ((size_t)b * C_ + c0) * K_;
#pragma unroll
    for (int k = 0; k < K_; k++) {
#pragma unroll
        for (int cc = 0; cc < CC; cc++) {
            unsigned int lo = (unsigned int)(acc[k][cc] & 0xffffffffULL);
            unsigned int hi = (unsigned int)(acc[k][cc] >> 32);
            float v = __uint_as_float(lo) + __uint_as_float(hi);
#pragma unroll
            for (int off = 16; off; off >>= 1)
                v += __shfl_xor_sync(0xffffffffu, v, off);
            if (lane == 0)
                orow[cc * K_ + k] = v * invp[k];
        }
    }
}

// ---------------------------------------------------------------------------
extern "C" void kernel_launch(void* const* d_in, const int* in_sizes, int n_in,
                              void* d_out, int out_size) {
    const float* feats = (const float*)d_in[0];   // (8, 512, 128, 128) fp32
    const float* probs = (const float*)d_in[1];   // (8, 19, 128, 128) fp32
    float* out = (float*)d_out;                   // (8, 512, 19, 1) fp32

    cudaFuncSetAttribute(ctx_k, cudaFuncAttributeMaxDynamicSharedMemorySize,
                         SMEM_FLOATS * (int)sizeof(float));

    softmax_k<<<B_ * K_, 256>>>(probs);
    ctx_k<<<dim3(C_ / CT, B_), 256, SMEM_FLOATS * sizeof(float)>>>(feats, out);
}